// round 2
// baseline (speedup 1.0000x reference)
#include <cuda_runtime.h>
#include <math.h>
#include <stdint.h>

// Shapes (fixed for this problem)
#define B_   64
#define Q_   64
#define T_   448
#define S_   512
#define D_   512
#define FD_  1024
#define H_   8
#define DH_  64
#define FF_  2048
#define NROWS (B_ * S_)   // 32768
#define VROWS (B_ * T_)   // 28672

// ---------------- scratch (device globals; no allocation) ----------------
__device__ float g_x  [NROWS * D_];
__device__ float g_q  [NROWS * D_];
__device__ float g_k  [NROWS * D_];
__device__ float g_v  [NROWS * D_];
__device__ float g_ctx[NROWS * D_];
__device__ float g_t  [NROWS * D_];
__device__ float g_ffn[NROWS * FF_];

#define NEG_INF __int_as_float(0xff800000)

// ---------------- block reduction ----------------
__device__ __forceinline__ float block_sum256(float v, float* red) {
    int lane = threadIdx.x & 31;
    int w    = threadIdx.x >> 5;
#pragma unroll
    for (int o = 16; o > 0; o >>= 1) v += __shfl_xor_sync(0xffffffffu, v, o);
    if (lane == 0) red[w] = v;
    __syncthreads();
    if (w == 0) {
        float r = (lane < 8) ? red[lane] : 0.f;
#pragma unroll
        for (int o = 4; o > 0; o >>= 1) r += __shfl_xor_sync(0xffffffffu, r, o);
        if (lane == 0) red[0] = r;
    }
    __syncthreads();
    float out = red[0];
    __syncthreads();
    return out;
}

// ---------------- LayerNorm over D=512, one block per row ----------------
__global__ __launch_bounds__(256)
void ln512(const float* __restrict__ in, const float* __restrict__ g,
           const float* __restrict__ b, float* __restrict__ out)
{
    __shared__ float red[32];
    size_t row = blockIdx.x;
    const float* x = in + row * D_;
    int c0 = threadIdx.x, c1 = threadIdx.x + 256;
    float v0 = x[c0], v1 = x[c1];
    float mean = block_sum256(v0 + v1, red) * (1.f / 512.f);
    float d0 = v0 - mean, d1 = v1 - mean;
    float var = block_sum256(d0 * d0 + d1 * d1, red) * (1.f / 512.f);
    float inv = 1.f / sqrtf(var + 1e-12f);
    float* o = out + row * D_;
    o[c0] = d0 * inv * g[c0] + b[c0];
    o[c1] = d1 * inv * g[c1] + b[c1];
}

// ---------------- assemble x = LN(concat(q, v) + pos + mod) ----------------
__global__ __launch_bounds__(256)
void assemble_ln(const float* __restrict__ question, const float* __restrict__ vproj,
                 const float* __restrict__ pos, const float* __restrict__ mod,
                 const float* __restrict__ g, const float* __restrict__ bb,
                 float* __restrict__ out)
{
    __shared__ float red[32];
    int row = blockIdx.x;
    int b = row >> 9, s = row & 511;
    int c0 = threadIdx.x, c1 = threadIdx.x + 256;
    float v0, v1;
    if (s < Q_) {
        const float* src = question + ((size_t)b * Q_ + s) * D_;
        v0 = src[c0]; v1 = src[c1];
    } else {
        const float* src = vproj + ((size_t)b * T_ + (s - Q_)) * D_;
        v0 = src[c0]; v1 = src[c1];
    }
    const float* me = mod + (s < Q_ ? 0 : 1) * D_;
    v0 += pos[s * D_ + c0] + me[c0];
    v1 += pos[s * D_ + c1] + me[c1];
    float mean = block_sum256(v0 + v1, red) * (1.f / 512.f);
    float d0 = v0 - mean, d1 = v1 - mean;
    float var = block_sum256(d0 * d0 + d1 * d1, red) * (1.f / 512.f);
    float inv = 1.f / sqrtf(var + 1e-12f);
    float* o = out + (size_t)row * D_;
    o[c0] = d0 * inv * g[c0] + bb[c0];
    o[c1] = d1 * inv * g[c1] + bb[c1];
}

// ---------------- SGEMM: C = A[MxK] @ B[KxN] + bias (+res) (opt GELU) ----------------
// 128x128 block tile, 16 K-slab, 256 threads, 8x8 per-thread micro-tile.
// Requires M%128==0, N%128==0, K%16==0 (true for all calls here).
template<bool GELU, bool RES>
__global__ __launch_bounds__(256)
void sgemm(const float* __restrict__ A, const float* __restrict__ Bm,
           const float* __restrict__ bias, const float* __restrict__ res,
           float* __restrict__ C, int M, int N, int K)
{
    __shared__ float As[16][136];   // transposed A slab, padded for alignment
    __shared__ float Bs[16][128];
    const int tid = threadIdx.x;
    const int tn = tid & 15, tm = tid >> 4;
    const int bn = blockIdx.x * 128, bm = blockIdx.y * 128;

    float acc[8][8] = {};

    for (int k0 = 0; k0 < K; k0 += 16) {
#pragma unroll
        for (int i = 0; i < 2; i++) {
            int id = tid + i * 256;         // 512 float4 in the A slab
            int ar = id >> 2;
            int ak = (id & 3) << 2;
            float4 va = *(const float4*)(A + (size_t)(bm + ar) * K + k0 + ak);
            As[ak + 0][ar] = va.x;
            As[ak + 1][ar] = va.y;
            As[ak + 2][ar] = va.z;
            As[ak + 3][ar] = va.w;
        }
#pragma unroll
        for (int i = 0; i < 2; i++) {
            int id = tid + i * 256;
            int bk = id >> 5;
            int bc = (id & 31) << 2;
            *(float4*)(&Bs[bk][bc]) = *(const float4*)(Bm + (size_t)(k0 + bk) * N + bn + bc);
        }
        __syncthreads();
#pragma unroll
        for (int kk = 0; kk < 16; kk++) {
            float4 a0 = *(float4*)&As[kk][tm * 8];
            float4 a1 = *(float4*)&As[kk][tm * 8 + 4];
            float4 b0 = *(float4*)&Bs[kk][tn * 8];
            float4 b1 = *(float4*)&Bs[kk][tn * 8 + 4];
            float a[8] = {a0.x, a0.y, a0.z, a0.w, a1.x, a1.y, a1.z, a1.w};
            float b[8] = {b0.x, b0.y, b0.z, b0.w, b1.x, b1.y, b1.z, b1.w};
#pragma unroll
            for (int i = 0; i < 8; i++)
#pragma unroll
                for (int j = 0; j < 8; j++)
                    acc[i][j] += a[i] * b[j];
        }
        __syncthreads();
    }

#pragma unroll
    for (int i = 0; i < 8; i++) {
        size_t r = bm + tm * 8 + i;
#pragma unroll
        for (int jj = 0; jj < 2; jj++) {
            int c = bn + tn * 8 + jj * 4;
            float vals[4];
#pragma unroll
            for (int j = 0; j < 4; j++) {
                float val = acc[i][jj * 4 + j] + bias[c + j];
                if (RES) val += res[r * N + c + j];
                if (GELU) val = 0.5f * val * (1.0f + erff(val * 0.70710678118654752f));
                vals[j] = val;
            }
            *(float4*)(C + r * N + c) = make_float4(vals[0], vals[1], vals[2], vals[3]);
        }
    }
}

// ---------------- Flash attention: 64-row Q tile, online softmax ----------------
// grid (S/64=8, H=8, B=64), 256 threads, dyn smem.
#define APAD 68
#define ATTN_SMEM ((4 * 64 * APAD + 3 * 64) * (int)sizeof(float))

__global__ __launch_bounds__(256)
void attn(const float* __restrict__ Qm, const float* __restrict__ Km,
          const float* __restrict__ Vm, const int* __restrict__ mask,
          float* __restrict__ O)
{
    extern __shared__ float sm[];
    float* Qs   = sm;                 // [64 q][APAD] (d)
    float* Kt   = Qs + 64 * APAD;     // [64 d][APAD] (k)  -- transposed
    float* Vs   = Kt + 64 * APAD;     // [64 k][APAD] (d)
    float* Ps   = Vs + 64 * APAD;     // [64 q][APAD] (k)  -- scores -> probs
    float* mrow = Ps + 64 * APAD;
    float* lrow = mrow + 64;
    float* arow = lrow + 64;

    const int qt = blockIdx.x, h = blockIdx.y, b = blockIdx.z;
    const int tid = threadIdx.x;
    const int tn = tid & 15, tm = tid >> 4;
    const int r0 = tm * 4, c0 = tn * 4;

#pragma unroll
    for (int i = 0; i < 4; i++) {
        int id = tid + i * 256;
        int r = id >> 4, c = (id & 15) << 2;
        *(float4*)&Qs[r * APAD + c] =
            *(const float4*)(Qm + (size_t)(b * S_ + qt * 64 + r) * D_ + h * DH_ + c);
    }
    if (tid < 64) { mrow[tid] = NEG_INF; lrow[tid] = 0.f; }
    float acc[4][4] = {};

    for (int kt = 0; kt < 8; kt++) {
        __syncthreads();   // previous tile fully consumed; init visible on kt==0
#pragma unroll
        for (int i = 0; i < 4; i++) {
            int id = tid + i * 256;
            int r = id >> 4, c = (id & 15) << 2;     // r = key idx, c = dh
            size_t base = (size_t)(b * S_ + kt * 64 + r) * D_ + h * DH_ + c;
            float4 kv = *(const float4*)(Km + base);
            Kt[(c + 0) * APAD + r] = kv.x;
            Kt[(c + 1) * APAD + r] = kv.y;
            Kt[(c + 2) * APAD + r] = kv.z;
            Kt[(c + 3) * APAD + r] = kv.w;
            *(float4*)&Vs[r * APAD + c] = *(const float4*)(Vm + base);
        }
        __syncthreads();

        // scores: Sc[4q][4k]
        float sc[4][4] = {};
#pragma unroll 8
        for (int d = 0; d < 64; d++) {
            float4 kf = *(float4*)&Kt[d * APAD + c0];
            float qv[4];
#pragma unroll
            for (int j = 0; j < 4; j++) qv[j] = Qs[(r0 + j) * APAD + d];
#pragma unroll
            for (int i = 0; i < 4; i++) {
                sc[i][0] += qv[i] * kf.x;
                sc[i][1] += qv[i] * kf.y;
                sc[i][2] += qv[i] * kf.z;
                sc[i][3] += qv[i] * kf.w;
            }
        }
        // scale + mask, publish to Ps
#pragma unroll
        for (int i = 0; i < 4; i++) {
#pragma unroll
            for (int j = 0; j < 4; j++) {
                float s = sc[i][j] * 0.125f;   // 1/sqrt(64)
                if (mask[b * S_ + kt * 64 + c0 + j] == 0) s = NEG_INF;
                Ps[(r0 + i) * APAD + c0 + j] = s;
            }
        }
        __syncthreads();

        // online softmax update, one thread per q row
        if (tid < 64) {
            float mold = mrow[tid];
            float mx = mold;
#pragma unroll
            for (int c = 0; c < 64; c++) mx = fmaxf(mx, Ps[tid * APAD + c]);
            float alpha = (mold == NEG_INF) ? 0.f : __expf(mold - mx);
            float sum = 0.f;
#pragma unroll
            for (int c = 0; c < 64; c++) {
                float p = __expf(Ps[tid * APAD + c] - mx);
                Ps[tid * APAD + c] = p;
                sum += p;
            }
            lrow[tid] = lrow[tid] * alpha + sum;
            mrow[tid] = mx;
            arow[tid] = alpha;
        }
        __syncthreads();

        float al[4];
#pragma unroll
        for (int i = 0; i < 4; i++) al[i] = arow[r0 + i];
#pragma unroll
        for (int i = 0; i < 4; i++)
#pragma unroll
            for (int j = 0; j < 4; j++) acc[i][j] *= al[i];

#pragma unroll 8
        for (int kk = 0; kk < 64; kk++) {
            float4 vf = *(float4*)&Vs[kk * APAD + c0];
            float pv[4];
#pragma unroll
            for (int i = 0; i < 4; i++) pv[i] = Ps[(r0 + i) * APAD + kk];
#pragma unroll
            for (int i = 0; i < 4; i++) {
                acc[i][0] += pv[i] * vf.x;
                acc[i][1] += pv[i] * vf.y;
                acc[i][2] += pv[i] * vf.z;
                acc[i][3] += pv[i] * vf.w;
            }
        }
    }
    __syncthreads();

#pragma unroll
    for (int i = 0; i < 4; i++) {
        float inv = 1.f / lrow[r0 + i];
        float4 o = make_float4(acc[i][0] * inv, acc[i][1] * inv,
                               acc[i][2] * inv, acc[i][3] * inv);
        *(float4*)(O + (size_t)(b * S_ + qt * 64 + r0 + i) * D_ + h * DH_ + c0) = o;
    }
}

// ---------------- orchestration ----------------
extern "C" void kernel_launch(void* const* d_in, const int* in_sizes, int n_in,
                              void* d_out, int out_size)
{
    (void)in_sizes; (void)n_in; (void)out_size;
    const float* video    = (const float*)d_in[0];
    const float* question = (const float*)d_in[1];
    const int*   mask     = (const int*)  d_in[2];
    const float* pos_emb  = (const float*)d_in[3];
    const float* mod_emb  = (const float*)d_in[4];
    const float* Wv   = (const float*)d_in[5];
    const float* bv   = (const float*)d_in[6];
    const float* nv_g = (const float*)d_in[7];
    const float* nv_b = (const float*)d_in[8];
    const float* emb_g= (const float*)d_in[9];
    const float* emb_b= (const float*)d_in[10];
    const float* Wq   = (const float*)d_in[11];
    const float* bq   = (const float*)d_in[12];
    const float* Wk   = (const float*)d_in[13];
    const float* bk   = (const float*)d_in[14];
    const float* Wva  = (const float*)d_in[15];
    const float* bva  = (const float*)d_in[16];
    const float* Wo   = (const float*)d_in[17];
    const float* bo   = (const float*)d_in[18];
    const float* ln1_g= (const float*)d_in[19];
    const float* ln1_b= (const float*)d_in[20];
    const float* W1   = (const float*)d_in[21];
    const float* b1   = (const float*)d_in[22];
    const float* W2   = (const float*)d_in[23];
    const float* b2   = (const float*)d_in[24];
    const float* ln2_g= (const float*)d_in[25];
    const float* ln2_b= (const float*)d_in[26];

    float *x, *q, *k, *v, *ctx, *t, *ffn;
    cudaGetSymbolAddress((void**)&x,   g_x);
    cudaGetSymbolAddress((void**)&q,   g_q);
    cudaGetSymbolAddress((void**)&k,   g_k);
    cudaGetSymbolAddress((void**)&v,   g_v);
    cudaGetSymbolAddress((void**)&ctx, g_ctx);
    cudaGetSymbolAddress((void**)&t,   g_t);
    cudaGetSymbolAddress((void**)&ffn, g_ffn);

    cudaFuncSetAttribute(attn, cudaFuncAttributeMaxDynamicSharedMemorySize, ATTN_SMEM);

    // video projection + LN(nv)
    sgemm<false, false><<<dim3(D_ / 128, VROWS / 128), 256>>>(
        video, Wv, bv, nullptr, t, VROWS, D_, FD_);
    ln512<<<VROWS, 256>>>(t, nv_g, nv_b, t);

    // assemble x = LN(concat + pos + mod)
    assemble_ln<<<NROWS, 256>>>(question, t, pos_emb, mod_emb, emb_g, emb_b, x);

    for (int i = 0; i < 2; i++) {
        const float* Wqi = Wq  + (size_t)i * D_ * D_;
        const float* Wki = Wk  + (size_t)i * D_ * D_;
        const float* Wvi = Wva + (size_t)i * D_ * D_;
        const float* Woi = Wo  + (size_t)i * D_ * D_;
        const float* W1i = W1  + (size_t)i * D_ * FF_;
        const float* W2i = W2  + (size_t)i * FF_ * D_;
        const float* bqi = bq + i * D_;
        const float* bki = bk + i * D_;
        const float* bvi = bva + i * D_;
        const float* boi = bo + i * D_;
        const float* b1i = b1 + i * FF_;
        const float* b2i = b2 + i * D_;

        sgemm<false, false><<<dim3(4, NROWS / 128), 256>>>(x, Wqi, bqi, nullptr, q, NROWS, D_, D_);
        sgemm<false, false><<<dim3(4, NROWS / 128), 256>>>(x, Wki, bki, nullptr, k, NROWS, D_, D_);
        sgemm<false, false><<<dim3(4, NROWS / 128), 256>>>(x, Wvi, bvi, nullptr, v, NROWS, D_, D_);

        attn<<<dim3(S_ / 64, H_, B_), 256, ATTN_SMEM>>>(q, k, v, mask, ctx);

        sgemm<false, true><<<dim3(4, NROWS / 128), 256>>>(ctx, Woi, boi, x, t, NROWS, D_, D_);
        ln512<<<NROWS, 256>>>(t, ln1_g + i * D_, ln1_b + i * D_, x);

        sgemm<true, false><<<dim3(FF_ / 128, NROWS / 128), 256>>>(x, W1i, b1i, nullptr, ffn, NROWS, FF_, D_);
        sgemm<false, true><<<dim3(4, NROWS / 128), 256>>>(ffn, W2i, b2i, x, t, NROWS, D_, FF_);

        float* out = (i == 1) ? (float*)d_out : x;
        ln512<<<NROWS, 256>>>(t, ln2_g + i * D_, ln2_b + i * D_, out);
    }
}

// round 7
// speedup vs baseline: 1.7686x; 1.7686x over previous
#include <cuda_runtime.h>
#include <cuda_bf16.h>
#include <math.h>
#include <stdint.h>

// Shapes (fixed for this problem)
#define B_   64
#define Q_   64
#define T_   448
#define S_   512
#define D_   512
#define FD_  1024
#define H_   8
#define DH_  64
#define FF_  2048
#define NROWS (B_ * S_)   // 32768
#define VROWS (B_ * T_)   // 28672

#define NEG_INF __int_as_float(0xff800000)

// ---------------- scratch (device globals; no allocation) ----------------
__device__ float g_x [NROWS * D_];
__device__ float g_q [NROWS * D_];
__device__ float g_k [NROWS * D_];
__device__ float g_v [NROWS * D_];
__device__ float g_t [NROWS * D_];

// split activations (bf16 hi/lo)
__device__ __nv_bfloat16 g_ah[(size_t)VROWS * FD_];
__device__ __nv_bfloat16 g_al[(size_t)VROWS * FD_];
__device__ __nv_bfloat16 g_bh[(size_t)NROWS * FF_];
__device__ __nv_bfloat16 g_bl[(size_t)NROWS * FF_];

// transposed+split weights [N, K] bf16
__device__ __nv_bfloat16 g_wvh[512 * 1024],      g_wvl[512 * 1024];
__device__ __nv_bfloat16 g_wqh[2 * 512 * 512],   g_wql[2 * 512 * 512];
__device__ __nv_bfloat16 g_wkh[2 * 512 * 512],   g_wkl[2 * 512 * 512];
__device__ __nv_bfloat16 g_wah[2 * 512 * 512],   g_wal[2 * 512 * 512];
__device__ __nv_bfloat16 g_woh[2 * 512 * 512],   g_wol[2 * 512 * 512];
__device__ __nv_bfloat16 g_w1h[2 * 2048 * 512],  g_w1l[2 * 2048 * 512];
__device__ __nv_bfloat16 g_w2h[2 * 512 * 2048],  g_w2l[2 * 512 * 2048];

// ---------------- helpers ----------------
__device__ __forceinline__ uint32_t smem_u32(const void* p) {
    uint32_t a;
    asm("{ .reg .u64 t; cvta.to.shared.u64 t, %1; cvt.u32.u64 %0, t; }" : "=r"(a) : "l"(p));
    return a;
}
__device__ __forceinline__ void cp16(uint32_t s, const void* g) {
    asm volatile("cp.async.cg.shared.global [%0], [%1], 16;" :: "r"(s), "l"(g));
}
#define CP_COMMIT()  asm volatile("cp.async.commit_group;" ::: "memory")
#define CP_WAIT0()   asm volatile("cp.async.wait_group 0;" ::: "memory")
#define CP_WAIT1()   asm volatile("cp.async.wait_group 1;" ::: "memory")

#define LDSM4(r0, r1, r2, r3, addr) \
    asm volatile("ldmatrix.sync.aligned.m8n8.x4.shared.b16 {%0,%1,%2,%3}, [%4];" \
        : "=r"(r0), "=r"(r1), "=r"(r2), "=r"(r3) : "r"(addr))

#define MMA16816(d, a, b) \
    asm volatile("mma.sync.aligned.m16n8k16.row.col.f32.bf16.bf16.f32 " \
        "{%0,%1,%2,%3}, {%4,%5,%6,%7}, {%8,%9}, {%0,%1,%2,%3};" \
        : "+f"((d)[0]), "+f"((d)[1]), "+f"((d)[2]), "+f"((d)[3]) \
        : "r"((a)[0]), "r"((a)[1]), "r"((a)[2]), "r"((a)[3]), \
          "r"((b)[0]), "r"((b)[1]))

__device__ __forceinline__ void split1(float v, __nv_bfloat16& h, __nv_bfloat16& l) {
    h = __float2bfloat16_rn(v);
    l = __float2bfloat16_rn(v - __bfloat162float(h));
}

// ---------------- split / transpose-split conversion ----------------
__global__ __launch_bounds__(256)
void split_k(const float4* __restrict__ src, __nv_bfloat162* __restrict__ hi,
             __nv_bfloat162* __restrict__ lo, int n4)
{
    for (int i = blockIdx.x * 256 + threadIdx.x; i < n4; i += gridDim.x * 256) {
        float4 v = src[i];
        __nv_bfloat16 h0, h1, h2, h3, l0, l1, l2, l3;
        split1(v.x, h0, l0); split1(v.y, h1, l1);
        split1(v.z, h2, l2); split1(v.w, h3, l3);
        hi[i * 2 + 0] = __nv_bfloat162(h0, h1);
        hi[i * 2 + 1] = __nv_bfloat162(h2, h3);
        lo[i * 2 + 0] = __nv_bfloat162(l0, l1);
        lo[i * 2 + 1] = __nv_bfloat162(l2, l3);
    }
}

// W [K,N] fp32 -> hi/lo [N,K] bf16 (transpose + split)
__global__ __launch_bounds__(256)
void tsplit_k(const float* __restrict__ W, __nv_bfloat16* __restrict__ hi,
              __nv_bfloat16* __restrict__ lo, int K, int N)
{
    __shared__ float tile[32][33];
    int n0 = blockIdx.x * 32, k0 = blockIdx.y * 32;
    int tid = threadIdx.x;
    int c = tid & 31;
#pragma unroll
    for (int i = 0; i < 4; i++) {
        int r = (tid >> 5) + i * 8;
        tile[r][c] = W[(size_t)(k0 + r) * N + n0 + c];
    }
    __syncthreads();
#pragma unroll
    for (int i = 0; i < 4; i++) {
        int rr = (tid >> 5) + i * 8;
        float v = tile[c][rr];
        __nv_bfloat16 h, l;
        split1(v, h, l);
        size_t o = (size_t)(n0 + rr) * K + k0 + c;
        hi[o] = h;
        lo[o] = l;
    }
}

// ---------------- mma.sync split-bf16 GEMM ----------------
// C[M,N] = A[M,K] @ Bt[N,K]^T + bias (+res) (opt GELU), fp32 or split-bf16 out.
// A as bf16 hi/lo [M,K]; B as bf16 hi/lo [N,K]. M%128==0, N%128==0, K%32==0.
// CTA 128x128, K-chunk 32, 8 warps (4m x 2n), warp tile 32x64, cp.async double buffer.
#define MG_ROWH 40                         // padded row length in halves
#define MG_MATH (128 * MG_ROWH)            // halves per matrix tile = 5120
#define MG_MATB (MG_MATH * 2)              // bytes per matrix tile  = 10240
#define MG_STGB (4 * MG_MATB)              // bytes per stage        = 40960
#define MG_SMEM (2 * MG_STGB)              // total dynamic smem     = 81920

__device__ __forceinline__ void mg_load(uint32_t s0,
    const __nv_bfloat16* __restrict__ Ah, const __nv_bfloat16* __restrict__ Al,
    const __nv_bfloat16* __restrict__ Bh, const __nv_bfloat16* __restrict__ Bl,
    int bm, int bn, int K, int k0, int tid)
{
#pragma unroll
    for (int i = 0; i < 2; i++) {
        int u = tid + (i << 8);
        int r = u >> 2, c8 = (u & 3) << 3;          // row, halves offset
        size_t ga = (size_t)(bm + r) * K + k0 + c8;
        size_t gb = (size_t)(bn + r) * K + k0 + c8;
        uint32_t s = s0 + (uint32_t)(r * MG_ROWH + c8) * 2;
        cp16(s,               Ah + ga);
        cp16(s + MG_MATB,     Al + ga);
        cp16(s + 2 * MG_MATB, Bh + gb);
        cp16(s + 3 * MG_MATB, Bl + gb);
    }
}

template<bool GELU, bool RES, bool SPLIT>
__global__ __launch_bounds__(256, 1)
void mgemm(const __nv_bfloat16* __restrict__ Ah, const __nv_bfloat16* __restrict__ Al,
           const __nv_bfloat16* __restrict__ Bh, const __nv_bfloat16* __restrict__ Bl,
           const float* __restrict__ bias, const float* __restrict__ res,
           float* __restrict__ C, __nv_bfloat16* __restrict__ Ch,
           __nv_bfloat16* __restrict__ Cl, int M, int N, int K)
{
    extern __shared__ char smem[];
    const uint32_t sbase = smem_u32(smem);
    const int tid = threadIdx.x;
    const int lane = tid & 31, wid = tid >> 5;
    const int wm = wid >> 1, wn = wid & 1;          // 4 x 2 warp grid
    const int bn = blockIdx.x * 128, bm = blockIdx.y * 128;

    float acc[2][8][4];
#pragma unroll
    for (int i = 0; i < 2; i++)
#pragma unroll
        for (int j = 0; j < 8; j++)
#pragma unroll
            for (int p = 0; p < 4; p++) acc[i][j][p] = 0.f;

    // ldmatrix lane addressing (constant per thread)
    // A: lanes 0-15 -> row rbase+lane, k+0 ; lanes 16-31 -> row rbase+(lane-16), k+8
    const int a_r  = (lane < 16) ? lane : (lane - 16);
    const int a_k  = (lane < 16) ? 0 : 8;
    // B: idx = lane&7, sel = lane>>3 ; row = nbase + (sel>>1)*8 + idx, k + (sel&1)*8
    const int b_r  = ((lane >> 4) << 3) + (lane & 7);
    const int b_k  = ((lane >> 3) & 1) << 3;

    // prologue: chunk 0 -> stage 0
    mg_load(sbase, Ah, Al, Bh, Bl, bm, bn, K, 0, tid);
    CP_COMMIT();

    const int NC = K >> 5;
    for (int c = 0; c < NC; c++) {
        if (c + 1 < NC) {
            mg_load(sbase + ((c + 1) & 1) * MG_STGB, Ah, Al, Bh, Bl,
                    bm, bn, K, (c + 1) << 5, tid);
            CP_COMMIT();
            CP_WAIT1();
        } else {
            CP_WAIT0();
        }
        __syncthreads();

        const uint32_t s0  = sbase + (c & 1) * MG_STGB;
        const uint32_t aH  = s0;
        const uint32_t aL  = s0 + MG_MATB;
        const uint32_t bH  = s0 + 2 * MG_MATB;
        const uint32_t bL  = s0 + 3 * MG_MATB;

#pragma unroll
        for (int ks = 0; ks < 2; ks++) {
            // load all B fragments for this k16 (8 n-blocks, hi+lo)
            uint32_t bhf[8][2], blf[8][2];
#pragma unroll
            for (int nb2 = 0; nb2 < 4; nb2++) {
                int row = wn * 64 + nb2 * 16 + b_r;
                int kof = ks * 16 + b_k;
                uint32_t off = (uint32_t)(row * MG_ROWH + kof) * 2;
                uint32_t r0, r1, r2, r3;
                LDSM4(r0, r1, r2, r3, bH + off);
                bhf[nb2 * 2][0] = r0; bhf[nb2 * 2][1] = r1;
                bhf[nb2 * 2 + 1][0] = r2; bhf[nb2 * 2 + 1][1] = r3;
                LDSM4(r0, r1, r2, r3, bL + off);
                blf[nb2 * 2][0] = r0; blf[nb2 * 2][1] = r1;
                blf[nb2 * 2 + 1][0] = r2; blf[nb2 * 2 + 1][1] = r3;
            }
#pragma unroll
            for (int mh = 0; mh < 2; mh++) {
                int row = wm * 32 + mh * 16 + a_r;
                int kof = ks * 16 + a_k;
                uint32_t off = (uint32_t)(row * MG_ROWH + kof) * 2;
                uint32_t ahf[4], alf[4];
                LDSM4(ahf[0], ahf[1], ahf[2], ahf[3], aH + off);
                LDSM4(alf[0], alf[1], alf[2], alf[3], aL + off);
#pragma unroll
                for (int nb = 0; nb < 8; nb++) {
                    MMA16816(acc[mh][nb], ahf, bhf[nb]);
                    MMA16816(acc[mh][nb], ahf, blf[nb]);
                    MMA16816(acc[mh][nb], alf, bhf[nb]);
                }
            }
        }
        __syncthreads();
    }

    // epilogue: regs -> gmem with bias/res/gelu/split
    const int g = lane >> 2, t4 = lane & 3;
#pragma unroll
    for (int mh = 0; mh < 2; mh++) {
#pragma unroll
        for (int nb = 0; nb < 8; nb++) {
            int col = bn + wn * 64 + nb * 8 + t4 * 2;
            float b0 = bias[col], b1 = bias[col + 1];
#pragma unroll
            for (int hf = 0; hf < 2; hf++) {
                int row = bm + wm * 32 + mh * 16 + g + hf * 8;
                float v0 = acc[mh][nb][hf * 2 + 0] + b0;
                float v1 = acc[mh][nb][hf * 2 + 1] + b1;
                if (RES) {
                    float2 rv = *(const float2*)(res + (size_t)row * N + col);
                    v0 += rv.x; v1 += rv.y;
                }
                if (GELU) {
                    v0 = 0.5f * v0 * (1.0f + erff(v0 * 0.70710678118654752f));
                    v1 = 0.5f * v1 * (1.0f + erff(v1 * 0.70710678118654752f));
                }
                if (SPLIT) {
                    __nv_bfloat16 h0, h1, l0, l1;
                    split1(v0, h0, l0);
                    split1(v1, h1, l1);
                    size_t o = (size_t)row * N + col;
                    *(__nv_bfloat162*)(Ch + o) = __nv_bfloat162(h0, h1);
                    *(__nv_bfloat162*)(Cl + o) = __nv_bfloat162(l0, l1);
                } else {
                    *(float2*)(C + (size_t)row * N + col) = make_float2(v0, v1);
                }
            }
        }
    }
}

// ---------------- block reduction ----------------
__device__ __forceinline__ float block_sum256(float v, float* red) {
    int lane = threadIdx.x & 31;
    int w    = threadIdx.x >> 5;
#pragma unroll
    for (int o = 16; o > 0; o >>= 1) v += __shfl_xor_sync(0xffffffffu, v, o);
    if (lane == 0) red[w] = v;
    __syncthreads();
    if (w == 0) {
        float r = (lane < 8) ? red[lane] : 0.f;
#pragma unroll
        for (int o = 4; o > 0; o >>= 1) r += __shfl_xor_sync(0xffffffffu, r, o);
        if (lane == 0) red[0] = r;
    }
    __syncthreads();
    float out = red[0];
    __syncthreads();
    return out;
}

// ---------------- LayerNorm over D=512 + optional split output ----------------
template<bool SPLIT>
__global__ __launch_bounds__(256)
void ln512(const float* __restrict__ in, const float* __restrict__ g,
           const float* __restrict__ b, float* __restrict__ out,
           __nv_bfloat16* __restrict__ oh, __nv_bfloat16* __restrict__ ol)
{
    __shared__ float red[32];
    size_t row = blockIdx.x;
    const float* x = in + row * D_;
    int c0 = threadIdx.x, c1 = threadIdx.x + 256;
    float v0 = x[c0], v1 = x[c1];
    float mean = block_sum256(v0 + v1, red) * (1.f / 512.f);
    float d0 = v0 - mean, d1 = v1 - mean;
    float var = block_sum256(d0 * d0 + d1 * d1, red) * (1.f / 512.f);
    float inv = 1.f / sqrtf(var + 1e-12f);
    float r0 = d0 * inv * g[c0] + b[c0];
    float r1 = d1 * inv * g[c1] + b[c1];
    out[row * D_ + c0] = r0;
    out[row * D_ + c1] = r1;
    if (SPLIT) {
        __nv_bfloat16 h0, h1, l0, l1;
        split1(r0, h0, l0);
        split1(r1, h1, l1);
        oh[row * D_ + c0] = h0; oh[row * D_ + c1] = h1;
        ol[row * D_ + c0] = l0; ol[row * D_ + c1] = l1;
    }
}

// ---------------- assemble x = LN(concat(q, v) + pos + mod), split out ----------------
__global__ __launch_bounds__(256)
void assemble_ln(const float* __restrict__ question, const float* __restrict__ vproj,
                 const float* __restrict__ pos, const float* __restrict__ mod,
                 const float* __restrict__ g, const float* __restrict__ bb,
                 float* __restrict__ out, __nv_bfloat16* __restrict__ oh,
                 __nv_bfloat16* __restrict__ ol)
{
    __shared__ float red[32];
    int row = blockIdx.x;
    int b = row >> 9, s = row & 511;
    int c0 = threadIdx.x, c1 = threadIdx.x + 256;
    float v0, v1;
    if (s < Q_) {
        const float* src = question + ((size_t)b * Q_ + s) * D_;
        v0 = src[c0]; v1 = src[c1];
    } else {
        const float* src = vproj + ((size_t)b * T_ + (s - Q_)) * D_;
        v0 = src[c0]; v1 = src[c1];
    }
    const float* me = mod + (s < Q_ ? 0 : 1) * D_;
    v0 += pos[s * D_ + c0] + me[c0];
    v1 += pos[s * D_ + c1] + me[c1];
    float mean = block_sum256(v0 + v1, red) * (1.f / 512.f);
    float d0 = v0 - mean, d1 = v1 - mean;
    float var = block_sum256(d0 * d0 + d1 * d1, red) * (1.f / 512.f);
    float inv = 1.f / sqrtf(var + 1e-12f);
    float r0 = d0 * inv * g[c0] + bb[c0];
    float r1 = d1 * inv * g[c1] + bb[c1];
    size_t o = (size_t)row * D_;
    out[o + c0] = r0;
    out[o + c1] = r1;
    __nv_bfloat16 h0, h1, l0, l1;
    split1(r0, h0, l0);
    split1(r1, h1, l1);
    oh[o + c0] = h0; oh[o + c1] = h1;
    ol[o + c0] = l0; ol[o + c1] = l1;
}

// ---------------- Flash attention (fp32): 64-row Q tile, online softmax ----------------
// Output written directly as split bf16 (feeds the Wo gemm).
#define APAD 68
#define ATTN_SMEM ((4 * 64 * APAD + 3 * 64) * (int)sizeof(float))

__global__ __launch_bounds__(256)
void attn(const float* __restrict__ Qm, const float* __restrict__ Km,
          const float* __restrict__ Vm, const int* __restrict__ mask,
          __nv_bfloat16* __restrict__ Oh, __nv_bfloat16* __restrict__ Ol)
{
    extern __shared__ float sm[];
    float* Qs   = sm;
    float* Kt   = Qs + 64 * APAD;
    float* Vs   = Kt + 64 * APAD;
    float* Ps   = Vs + 64 * APAD;
    float* mrow = Ps + 64 * APAD;
    float* lrow = mrow + 64;
    float* arow = lrow + 64;

    const int qt = blockIdx.x, h = blockIdx.y, b = blockIdx.z;
    const int tid = threadIdx.x;
    const int tn = tid & 15, tm = tid >> 4;
    const int r0 = tm * 4, c0 = tn * 4;

#pragma unroll
    for (int i = 0; i < 4; i++) {
        int id = tid + i * 256;
        int r = id >> 4, c = (id & 15) << 2;
        *(float4*)&Qs[r * APAD + c] =
            *(const float4*)(Qm + (size_t)(b * S_ + qt * 64 + r) * D_ + h * DH_ + c);
    }
    if (tid < 64) { mrow[tid] = NEG_INF; lrow[tid] = 0.f; }
    float acc[4][4] = {};

    for (int kt = 0; kt < 8; kt++) {
        __syncthreads();
#pragma unroll
        for (int i = 0; i < 4; i++) {
            int id = tid + i * 256;
            int r = id >> 4, c = (id & 15) << 2;
            size_t base = (size_t)(b * S_ + kt * 64 + r) * D_ + h * DH_ + c;
            float4 kv = *(const float4*)(Km + base);
            Kt[(c + 0) * APAD + r] = kv.x;
            Kt[(c + 1) * APAD + r] = kv.y;
            Kt[(c + 2) * APAD + r] = kv.z;
            Kt[(c + 3) * APAD + r] = kv.w;
            *(float4*)&Vs[r * APAD + c] = *(const float4*)(Vm + base);
        }
        __syncthreads();

        float sc[4][4] = {};
#pragma unroll 8
        for (int d = 0; d < 64; d++) {
            float4 kf = *(float4*)&Kt[d * APAD + c0];
            float qv[4];
#pragma unroll
            for (int j = 0; j < 4; j++) qv[j] = Qs[(r0 + j) * APAD + d];
#pragma unroll
            for (int i = 0; i < 4; i++) {
                sc[i][0] += qv[i] * kf.x;
                sc[i][1] += qv[i] * kf.y;
                sc[i][2] += qv[i] * kf.z;
                sc[i][3] += qv[i] * kf.w;
            }
        }
#pragma unroll
        for (int i = 0; i < 4; i++) {
#pragma unroll
            for (int j = 0; j < 4; j++) {
                float s = sc[i][j] * 0.125f;
                if (mask[b * S_ + kt * 64 + c0 + j] == 0) s = NEG_INF;
                Ps[(r0 + i) * APAD + c0 + j] = s;
            }
        }
        __syncthreads();

        if (tid < 64) {
            float mold = mrow[tid];
            float mx = mold;
#pragma unroll
            for (int c = 0; c < 64; c++) mx = fmaxf(mx, Ps[tid * APAD + c]);
            float alpha = (mold == NEG_INF) ? 0.f : __expf(mold - mx);
            float sum = 0.f;
#pragma unroll
            for (int c = 0; c < 64; c++) {
                float p = __expf(Ps[tid * APAD + c] - mx);
                Ps[tid * APAD + c] = p;
                sum += p;
            }
            lrow[tid] = lrow[tid] * alpha + sum;
            mrow[tid] = mx;
            arow[tid] = alpha;
        }
        __syncthreads();

        float al[4];
#pragma unroll
        for (int i = 0; i < 4; i++) al[i] = arow[r0 + i];
#pragma unroll
        for (int i = 0; i < 4; i++)
#pragma unroll
            for (int j = 0; j < 4; j++) acc[i][j] *= al[i];

#pragma unroll 8
        for (int kk = 0; kk < 64; kk++) {
            float4 vf = *(float4*)&Vs[kk * APAD + c0];
            float pv[4];
#pragma unroll
            for (int i = 0; i < 4; i++) pv[i] = Ps[(r0 + i) * APAD + kk];
#pragma unroll
            for (int i = 0; i < 4; i++) {
                acc[i][0] += pv[i] * vf.x;
                acc[i][1] += pv[i] * vf.y;
                acc[i][2] += pv[i] * vf.z;
                acc[i][3] += pv[i] * vf.w;
            }
        }
    }
    __syncthreads();

#pragma unroll
    for (int i = 0; i < 4; i++) {
        float inv = 1.f / lrow[r0 + i];
        float o0 = acc[i][0] * inv, o1 = acc[i][1] * inv;
        float o2 = acc[i][2] * inv, o3 = acc[i][3] * inv;
        __nv_bfloat16 h0, h1, h2, h3, l0, l1, l2, l3;
        split1(o0, h0, l0); split1(o1, h1, l1);
        split1(o2, h2, l2); split1(o3, h3, l3);
        size_t base = (size_t)(b * S_ + qt * 64 + r0 + i) * D_ + h * DH_ + c0;
        *(__nv_bfloat162*)(Oh + base)     = __nv_bfloat162(h0, h1);
        *(__nv_bfloat162*)(Oh + base + 2) = __nv_bfloat162(h2, h3);
        *(__nv_bfloat162*)(Ol + base)     = __nv_bfloat162(l0, l1);
        *(__nv_bfloat162*)(Ol + base + 2) = __nv_bfloat162(l2, l3);
    }
}

// ---------------- orchestration ----------------
extern "C" void kernel_launch(void* const* d_in, const int* in_sizes, int n_in,
                              void* d_out, int out_size)
{
    (void)in_sizes; (void)n_in; (void)out_size;
    const float* video    = (const float*)d_in[0];
    const float* question = (const float*)d_in[1];
    const int*   mask     = (const int*)  d_in[2];
    const float* pos_emb  = (const float*)d_in[3];
    const float* mod_emb  = (const float*)d_in[4];
    const float* Wv   = (const float*)d_in[5];
    const float* bv   = (const float*)d_in[6];
    const float* nv_g = (const float*)d_in[7];
    const float* nv_b = (const float*)d_in[8];
    const float* emb_g= (const float*)d_in[9];
    const float* emb_b= (const float*)d_in[10];
    const float* Wq   = (const float*)d_in[11];
    const float* bq   = (const float*)d_in[12];
    const float* Wk   = (const float*)d_in[13];
    const float* bk   = (const float*)d_in[14];
    const float* Wva  = (const float*)d_in[15];
    const float* bva  = (const float*)d_in[16];
    const float* Wo   = (const float*)d_in[17];
    const float* bo   = (const float*)d_in[18];
    const float* ln1_g= (const float*)d_in[19];
    const float* ln1_b= (const float*)d_in[20];
    const float* W1   = (const float*)d_in[21];
    const float* b1   = (const float*)d_in[22];
    const float* W2   = (const float*)d_in[23];
    const float* b2   = (const float*)d_in[24];
    const float* ln2_g= (const float*)d_in[25];
    const float* ln2_b= (const float*)d_in[26];

    float *x, *q, *k, *v, *t;
    cudaGetSymbolAddress((void**)&x, g_x);
    cudaGetSymbolAddress((void**)&q, g_q);
    cudaGetSymbolAddress((void**)&k, g_k);
    cudaGetSymbolAddress((void**)&v, g_v);
    cudaGetSymbolAddress((void**)&t, g_t);

    __nv_bfloat16 *ah, *al, *bh, *bl, *wvh, *wvl, *wqh, *wql, *wkh, *wkl,
                  *wah, *wal, *woh, *wol, *w1h, *w1l, *w2h, *w2l;
    cudaGetSymbolAddress((void**)&ah,  g_ah);
    cudaGetSymbolAddress((void**)&al,  g_al);
    cudaGetSymbolAddress((void**)&bh,  g_bh);
    cudaGetSymbolAddress((void**)&bl,  g_bl);
    cudaGetSymbolAddress((void**)&wvh, g_wvh);
    cudaGetSymbolAddress((void**)&wvl, g_wvl);
    cudaGetSymbolAddress((void**)&wqh, g_wqh);
    cudaGetSymbolAddress((void**)&wql, g_wql);
    cudaGetSymbolAddress((void**)&wkh, g_wkh);
    cudaGetSymbolAddress((void**)&wkl, g_wkl);
    cudaGetSymbolAddress((void**)&wah, g_wah);
    cudaGetSymbolAddress((void**)&wal, g_wal);
    cudaGetSymbolAddress((void**)&woh, g_woh);
    cudaGetSymbolAddress((void**)&wol, g_wol);
    cudaGetSymbolAddress((void**)&w1h, g_w1h);
    cudaGetSymbolAddress((void**)&w1l, g_w1l);
    cudaGetSymbolAddress((void**)&w2h, g_w2h);
    cudaGetSymbolAddress((void**)&w2l, g_w2l);

    cudaFuncSetAttribute(attn, cudaFuncAttributeMaxDynamicSharedMemorySize, ATTN_SMEM);
    cudaFuncSetAttribute(mgemm<false, false, false>, cudaFuncAttributeMaxDynamicSharedMemorySize, MG_SMEM);
    cudaFuncSetAttribute(mgemm<false, true,  false>, cudaFuncAttributeMaxDynamicSharedMemorySize, MG_SMEM);
    cudaFuncSetAttribute(mgemm<true,  false, true >, cudaFuncAttributeMaxDynamicSharedMemorySize, MG_SMEM);

    // ---- weight conversion (transpose + split), once per launch ----
    tsplit_k<<<dim3(512 / 32, 1024 / 32), 256>>>(Wv, wvh, wvl, 1024, 512);
    for (int i = 0; i < 2; i++) {
        size_t od = (size_t)i * 512 * 512;
        tsplit_k<<<dim3(16, 16), 256>>>(Wq  + od, wqh + od, wql + od, 512, 512);
        tsplit_k<<<dim3(16, 16), 256>>>(Wk  + od, wkh + od, wkl + od, 512, 512);
        tsplit_k<<<dim3(16, 16), 256>>>(Wva + od, wah + od, wal + od, 512, 512);
        tsplit_k<<<dim3(16, 16), 256>>>(Wo  + od, woh + od, wol + od, 512, 512);
        size_t of = (size_t)i * 512 * 2048;
        tsplit_k<<<dim3(2048 / 32, 512 / 32), 256>>>(W1 + of, w1h + of, w1l + of, 512, 2048);
        tsplit_k<<<dim3(512 / 32, 2048 / 32), 256>>>(W2 + of, w2h + of, w2l + of, 2048, 512);
    }

    // ---- video projection + LN(nv) ----
    split_k<<<2048, 256>>>((const float4*)video, (__nv_bfloat162*)ah,
                           (__nv_bfloat162*)al, (int)((size_t)VROWS * FD_ / 4));
    mgemm<false, false, false><<<dim3(D_ / 128, VROWS / 128), 256, MG_SMEM>>>(
        ah, al, wvh, wvl, bv, nullptr, t, nullptr, nullptr, VROWS, D_, FD_);
    ln512<false><<<VROWS, 256>>>(t, nv_g, nv_b, t, nullptr, nullptr);

    // ---- assemble x = LN(concat + pos + mod); writes x fp32 + ah/al split ----
    assemble_ln<<<NROWS, 256>>>(question, t, pos_emb, mod_emb, emb_g, emb_b, x, ah, al);

    for (int i = 0; i < 2; i++) {
        size_t od = (size_t)i * 512 * 512;
        size_t of = (size_t)i * 512 * 2048;
        const float* bqi = bq + i * D_;
        const float* bki = bk + i * D_;
        const float* bvi = bva + i * D_;
        const float* boi = bo + i * D_;
        const float* b1i = b1 + i * FF_;
        const float* b2i = b2 + i * D_;

        // QKV projections from ah/al (split of x)
        mgemm<false, false, false><<<dim3(4, NROWS / 128), 256, MG_SMEM>>>(
            ah, al, wqh + od, wql + od, bqi, nullptr, q, nullptr, nullptr, NROWS, D_, D_);
        mgemm<false, false, false><<<dim3(4, NROWS / 128), 256, MG_SMEM>>>(
            ah, al, wkh + od, wkl + od, bki, nullptr, k, nullptr, nullptr, NROWS, D_, D_);
        mgemm<false, false, false><<<dim3(4, NROWS / 128), 256, MG_SMEM>>>(
            ah, al, wah + od, wal + od, bvi, nullptr, v, nullptr, nullptr, NROWS, D_, D_);

        // attention -> ctx split (bh/bl, viewed [NROWS, D])
        attn<<<dim3(S_ / 64, H_, B_), 256, ATTN_SMEM>>>(q, k, v, mask, bh, bl);

        // output projection + residual, LN1 (-> x fp32 + ah/al split)
        mgemm<false, true, false><<<dim3(4, NROWS / 128), 256, MG_SMEM>>>(
            bh, bl, woh + od, wol + od, boi, x, t, nullptr, nullptr, NROWS, D_, D_);
        ln512<true><<<NROWS, 256>>>(t, ln1_g + i * D_, ln1_b + i * D_, x, ah, al);

        // FFN: W1+GELU writes split bf16 (bh/bl, [NROWS, FF]); W2 + residual
        mgemm<true, false, true><<<dim3(FF_ / 128, NROWS / 128), 256, MG_SMEM>>>(
            ah, al, w1h + of, w1l + of, b1i, nullptr, nullptr, bh, bl, NROWS, FF_, D_);
        mgemm<false, true, false><<<dim3(4, NROWS / 128), 256, MG_SMEM>>>(
            bh, bl, w2h + of, w2l + of, b2i, x, t, nullptr, nullptr, NROWS, D_, FF_);

        float* out = (i == 1) ? (float*)d_out : x;
        ln512<true><<<NROWS, 256>>>(t, ln2_g + i * D_, ln2_b + i * D_, out, ah, al);
    }
}

// round 8
// speedup vs baseline: 2.1848x; 1.2353x over previous
#include <cuda_runtime.h>
#include <cuda_bf16.h>
#include <math.h>
#include <stdint.h>

// Shapes (fixed for this problem)
#define B_   64
#define Q_   64
#define T_   448
#define S_   512
#define D_   512
#define FD_  1024
#define H_   8
#define DH_  64
#define FF_  2048
#define NROWS (B_ * S_)   // 32768
#define VROWS (B_ * T_)   // 28672
#define QKVN 1536

#define NEG_INF __int_as_float(0xff800000)

// ---------------- scratch (device globals; no allocation) ----------------
__device__ float g_x [NROWS * D_];
__device__ float g_t [NROWS * D_];

// split activations (bf16 hi/lo)
__device__ __nv_bfloat16 g_ah[(size_t)VROWS * FD_];
__device__ __nv_bfloat16 g_al[(size_t)VROWS * FD_];
__device__ __nv_bfloat16 g_bh[(size_t)NROWS * FF_];
__device__ __nv_bfloat16 g_bl[(size_t)NROWS * FF_];
// fused QKV output, split
__device__ __nv_bfloat16 g_qkvh[(size_t)NROWS * QKVN];
__device__ __nv_bfloat16 g_qkvl[(size_t)NROWS * QKVN];

// transposed+split weights [N, K] bf16
__device__ __nv_bfloat16 g_wvh[512 * 1024],      g_wvl[512 * 1024];
__device__ __nv_bfloat16 g_wqkvh[2 * QKVN * 512], g_wqkvl[2 * QKVN * 512];
__device__ __nv_bfloat16 g_woh[2 * 512 * 512],   g_wol[2 * 512 * 512];
__device__ __nv_bfloat16 g_w1h[2 * 2048 * 512],  g_w1l[2 * 2048 * 512];
__device__ __nv_bfloat16 g_w2h[2 * 512 * 2048],  g_w2l[2 * 512 * 2048];
__device__ float g_bqkv[2 * QKVN];

// ---------------- helpers ----------------
__device__ __forceinline__ uint32_t smem_u32(const void* p) {
    uint32_t a;
    asm("{ .reg .u64 t; cvta.to.shared.u64 t, %1; cvt.u32.u64 %0, t; }" : "=r"(a) : "l"(p));
    return a;
}
__device__ __forceinline__ void cp16(uint32_t s, const void* g) {
    asm volatile("cp.async.cg.shared.global [%0], [%1], 16;" :: "r"(s), "l"(g));
}
#define CP_COMMIT()  asm volatile("cp.async.commit_group;" ::: "memory")
#define CP_WAIT0()   asm volatile("cp.async.wait_group 0;" ::: "memory")
#define CP_WAIT1()   asm volatile("cp.async.wait_group 1;" ::: "memory")

#define LDSM4(r0, r1, r2, r3, addr) \
    asm volatile("ldmatrix.sync.aligned.m8n8.x4.shared.b16 {%0,%1,%2,%3}, [%4];" \
        : "=r"(r0), "=r"(r1), "=r"(r2), "=r"(r3) : "r"(addr))
#define LDSM4T(r0, r1, r2, r3, addr) \
    asm volatile("ldmatrix.sync.aligned.m8n8.x4.trans.shared.b16 {%0,%1,%2,%3}, [%4];" \
        : "=r"(r0), "=r"(r1), "=r"(r2), "=r"(r3) : "r"(addr))

#define MMA16816(d, a, b) \
    asm volatile("mma.sync.aligned.m16n8k16.row.col.f32.bf16.bf16.f32 " \
        "{%0,%1,%2,%3}, {%4,%5,%6,%7}, {%8,%9}, {%0,%1,%2,%3};" \
        : "+f"((d)[0]), "+f"((d)[1]), "+f"((d)[2]), "+f"((d)[3]) \
        : "r"((a)[0]), "r"((a)[1]), "r"((a)[2]), "r"((a)[3]), \
          "r"((b)[0]), "r"((b)[1]))

__device__ __forceinline__ void split1(float v, __nv_bfloat16& h, __nv_bfloat16& l) {
    h = __float2bfloat16_rn(v);
    l = __float2bfloat16_rn(v - __bfloat162float(h));
}
__device__ __forceinline__ uint32_t packh2(float a, float b) {
    __nv_bfloat162 t = __floats2bfloat162_rn(a, b);
    return *(uint32_t*)&t;
}

// ---------------- split / transpose-split conversion ----------------
__global__ __launch_bounds__(256)
void split_k(const float4* __restrict__ src, __nv_bfloat162* __restrict__ hi,
             __nv_bfloat162* __restrict__ lo, int n4)
{
    for (int i = blockIdx.x * 256 + threadIdx.x; i < n4; i += gridDim.x * 256) {
        float4 v = src[i];
        __nv_bfloat16 h0, h1, h2, h3, l0, l1, l2, l3;
        split1(v.x, h0, l0); split1(v.y, h1, l1);
        split1(v.z, h2, l2); split1(v.w, h3, l3);
        hi[i * 2 + 0] = __nv_bfloat162(h0, h1);
        hi[i * 2 + 1] = __nv_bfloat162(h2, h3);
        lo[i * 2 + 0] = __nv_bfloat162(l0, l1);
        lo[i * 2 + 1] = __nv_bfloat162(l2, l3);
    }
}

// W [K,N] fp32 -> hi/lo [N,K] bf16 (transpose + split)
__global__ __launch_bounds__(256)
void tsplit_k(const float* __restrict__ W, __nv_bfloat16* __restrict__ hi,
              __nv_bfloat16* __restrict__ lo, int K, int N)
{
    __shared__ float tile[32][33];
    int n0 = blockIdx.x * 32, k0 = blockIdx.y * 32;
    int tid = threadIdx.x;
    int c = tid & 31;
#pragma unroll
    for (int i = 0; i < 4; i++) {
        int r = (tid >> 5) + i * 8;
        tile[r][c] = W[(size_t)(k0 + r) * N + n0 + c];
    }
    __syncthreads();
#pragma unroll
    for (int i = 0; i < 4; i++) {
        int rr = (tid >> 5) + i * 8;
        float v = tile[c][rr];
        __nv_bfloat16 h, l;
        split1(v, h, l);
        size_t o = (size_t)(n0 + rr) * K + k0 + c;
        hi[o] = h;
        lo[o] = l;
    }
}

__global__ void pack_bias3(const float* __restrict__ bq, const float* __restrict__ bk,
                           const float* __restrict__ bv, float* __restrict__ out)
{
    int i = blockIdx.x * 256 + threadIdx.x;
    if (i < 512) {
        out[i]        = bq[i];
        out[512 + i]  = bk[i];
        out[1024 + i] = bv[i];
    }
}

// ---------------- mma.sync split-bf16 GEMM ----------------
#define MG_ROWH 40
#define MG_MATH (128 * MG_ROWH)
#define MG_MATB (MG_MATH * 2)
#define MG_STGB (4 * MG_MATB)
#define MG_SMEM (2 * MG_STGB)

__device__ __forceinline__ void mg_load(uint32_t s0,
    const __nv_bfloat16* __restrict__ Ah, const __nv_bfloat16* __restrict__ Al,
    const __nv_bfloat16* __restrict__ Bh, const __nv_bfloat16* __restrict__ Bl,
    int bm, int bn, int K, int k0, int tid)
{
#pragma unroll
    for (int i = 0; i < 2; i++) {
        int u = tid + (i << 8);
        int r = u >> 2, c8 = (u & 3) << 3;
        size_t ga = (size_t)(bm + r) * K + k0 + c8;
        size_t gb = (size_t)(bn + r) * K + k0 + c8;
        uint32_t s = s0 + (uint32_t)(r * MG_ROWH + c8) * 2;
        cp16(s,               Ah + ga);
        cp16(s + MG_MATB,     Al + ga);
        cp16(s + 2 * MG_MATB, Bh + gb);
        cp16(s + 3 * MG_MATB, Bl + gb);
    }
}

template<bool GELU, bool RES, bool SPLIT>
__global__ __launch_bounds__(256, 1)
void mgemm(const __nv_bfloat16* __restrict__ Ah, const __nv_bfloat16* __restrict__ Al,
           const __nv_bfloat16* __restrict__ Bh, const __nv_bfloat16* __restrict__ Bl,
           const float* __restrict__ bias, const float* __restrict__ res,
           float* __restrict__ C, __nv_bfloat16* __restrict__ Ch,
           __nv_bfloat16* __restrict__ Cl, int M, int N, int K)
{
    extern __shared__ char smem[];
    const uint32_t sbase = smem_u32(smem);
    const int tid = threadIdx.x;
    const int lane = tid & 31, wid = tid >> 5;
    const int wm = wid >> 1, wn = wid & 1;
    const int bn = blockIdx.x * 128, bm = blockIdx.y * 128;

    float acc[2][8][4];
#pragma unroll
    for (int i = 0; i < 2; i++)
#pragma unroll
        for (int j = 0; j < 8; j++)
#pragma unroll
            for (int p = 0; p < 4; p++) acc[i][j][p] = 0.f;

    const int a_r  = (lane < 16) ? lane : (lane - 16);
    const int a_k  = (lane < 16) ? 0 : 8;
    const int b_r  = ((lane >> 4) << 3) + (lane & 7);
    const int b_k  = ((lane >> 3) & 1) << 3;

    mg_load(sbase, Ah, Al, Bh, Bl, bm, bn, K, 0, tid);
    CP_COMMIT();

    const int NC = K >> 5;
    for (int c = 0; c < NC; c++) {
        if (c + 1 < NC) {
            mg_load(sbase + ((c + 1) & 1) * MG_STGB, Ah, Al, Bh, Bl,
                    bm, bn, K, (c + 1) << 5, tid);
            CP_COMMIT();
            CP_WAIT1();
        } else {
            CP_WAIT0();
        }
        __syncthreads();

        const uint32_t s0  = sbase + (c & 1) * MG_STGB;
        const uint32_t aH  = s0;
        const uint32_t aL  = s0 + MG_MATB;
        const uint32_t bH  = s0 + 2 * MG_MATB;
        const uint32_t bL  = s0 + 3 * MG_MATB;

#pragma unroll
        for (int ks = 0; ks < 2; ks++) {
            uint32_t bhf[8][2], blf[8][2];
#pragma unroll
            for (int nb2 = 0; nb2 < 4; nb2++) {
                int row = wn * 64 + nb2 * 16 + b_r;
                int kof = ks * 16 + b_k;
                uint32_t off = (uint32_t)(row * MG_ROWH + kof) * 2;
                uint32_t r0, r1, r2, r3;
                LDSM4(r0, r1, r2, r3, bH + off);
                bhf[nb2 * 2][0] = r0; bhf[nb2 * 2][1] = r1;
                bhf[nb2 * 2 + 1][0] = r2; bhf[nb2 * 2 + 1][1] = r3;
                LDSM4(r0, r1, r2, r3, bL + off);
                blf[nb2 * 2][0] = r0; blf[nb2 * 2][1] = r1;
                blf[nb2 * 2 + 1][0] = r2; blf[nb2 * 2 + 1][1] = r3;
            }
#pragma unroll
            for (int mh = 0; mh < 2; mh++) {
                int row = wm * 32 + mh * 16 + a_r;
                int kof = ks * 16 + a_k;
                uint32_t off = (uint32_t)(row * MG_ROWH + kof) * 2;
                uint32_t ahf[4], alf[4];
                LDSM4(ahf[0], ahf[1], ahf[2], ahf[3], aH + off);
                LDSM4(alf[0], alf[1], alf[2], alf[3], aL + off);
#pragma unroll
                for (int nb = 0; nb < 8; nb++) {
                    MMA16816(acc[mh][nb], ahf, bhf[nb]);
                    MMA16816(acc[mh][nb], ahf, blf[nb]);
                    MMA16816(acc[mh][nb], alf, bhf[nb]);
                }
            }
        }
        __syncthreads();
    }

    const int g = lane >> 2, t4 = lane & 3;
#pragma unroll
    for (int mh = 0; mh < 2; mh++) {
#pragma unroll
        for (int nb = 0; nb < 8; nb++) {
            int col = bn + wn * 64 + nb * 8 + t4 * 2;
            float b0 = bias[col], b1 = bias[col + 1];
#pragma unroll
            for (int hf = 0; hf < 2; hf++) {
                int row = bm + wm * 32 + mh * 16 + g + hf * 8;
                float v0 = acc[mh][nb][hf * 2 + 0] + b0;
                float v1 = acc[mh][nb][hf * 2 + 1] + b1;
                if (RES) {
                    float2 rv = *(const float2*)(res + (size_t)row * N + col);
                    v0 += rv.x; v1 += rv.y;
                }
                if (GELU) {
                    v0 = 0.5f * v0 * (1.0f + erff(v0 * 0.70710678118654752f));
                    v1 = 0.5f * v1 * (1.0f + erff(v1 * 0.70710678118654752f));
                }
                if (SPLIT) {
                    __nv_bfloat16 h0, h1, l0, l1;
                    split1(v0, h0, l0);
                    split1(v1, h1, l1);
                    size_t o = (size_t)row * N + col;
                    *(__nv_bfloat162*)(Ch + o) = __nv_bfloat162(h0, h1);
                    *(__nv_bfloat162*)(Cl + o) = __nv_bfloat162(l0, l1);
                } else {
                    *(float2*)(C + (size_t)row * N + col) = make_float2(v0, v1);
                }
            }
        }
    }
}

// ---------------- block reduction ----------------
__device__ __forceinline__ float block_sum256(float v, float* red) {
    int lane = threadIdx.x & 31;
    int w    = threadIdx.x >> 5;
#pragma unroll
    for (int o = 16; o > 0; o >>= 1) v += __shfl_xor_sync(0xffffffffu, v, o);
    if (lane == 0) red[w] = v;
    __syncthreads();
    if (w == 0) {
        float r = (lane < 8) ? red[lane] : 0.f;
#pragma unroll
        for (int o = 4; o > 0; o >>= 1) r += __shfl_xor_sync(0xffffffffu, r, o);
        if (lane == 0) red[0] = r;
    }
    __syncthreads();
    float out = red[0];
    __syncthreads();
    return out;
}

// ---------------- LayerNorm over D=512 + optional split output ----------------
template<bool SPLIT>
__global__ __launch_bounds__(256)
void ln512(const float* __restrict__ in, const float* __restrict__ g,
           const float* __restrict__ b, float* __restrict__ out,
           __nv_bfloat16* __restrict__ oh, __nv_bfloat16* __restrict__ ol)
{
    __shared__ float red[32];
    size_t row = blockIdx.x;
    const float* x = in + row * D_;
    int c0 = threadIdx.x, c1 = threadIdx.x + 256;
    float v0 = x[c0], v1 = x[c1];
    float mean = block_sum256(v0 + v1, red) * (1.f / 512.f);
    float d0 = v0 - mean, d1 = v1 - mean;
    float var = block_sum256(d0 * d0 + d1 * d1, red) * (1.f / 512.f);
    float inv = 1.f / sqrtf(var + 1e-12f);
    float r0 = d0 * inv * g[c0] + b[c0];
    float r1 = d1 * inv * g[c1] + b[c1];
    out[row * D_ + c0] = r0;
    out[row * D_ + c1] = r1;
    if (SPLIT) {
        __nv_bfloat16 h0, h1, l0, l1;
        split1(r0, h0, l0);
        split1(r1, h1, l1);
        oh[row * D_ + c0] = h0; oh[row * D_ + c1] = h1;
        ol[row * D_ + c0] = l0; ol[row * D_ + c1] = l1;
    }
}

// ---------------- assemble x = LN(concat(q, v) + pos + mod), split out ----------------
__global__ __launch_bounds__(256)
void assemble_ln(const float* __restrict__ question, const float* __restrict__ vproj,
                 const float* __restrict__ pos, const float* __restrict__ mod,
                 const float* __restrict__ g, const float* __restrict__ bb,
                 float* __restrict__ out, __nv_bfloat16* __restrict__ oh,
                 __nv_bfloat16* __restrict__ ol)
{
    __shared__ float red[32];
    int row = blockIdx.x;
    int b = row >> 9, s = row & 511;
    int c0 = threadIdx.x, c1 = threadIdx.x + 256;
    float v0, v1;
    if (s < Q_) {
        const float* src = question + ((size_t)b * Q_ + s) * D_;
        v0 = src[c0]; v1 = src[c1];
    } else {
        const float* src = vproj + ((size_t)b * T_ + (s - Q_)) * D_;
        v0 = src[c0]; v1 = src[c1];
    }
    const float* me = mod + (s < Q_ ? 0 : 1) * D_;
    v0 += pos[s * D_ + c0] + me[c0];
    v1 += pos[s * D_ + c1] + me[c1];
    float mean = block_sum256(v0 + v1, red) * (1.f / 512.f);
    float d0 = v0 - mean, d1 = v1 - mean;
    float var = block_sum256(d0 * d0 + d1 * d1, red) * (1.f / 512.f);
    float inv = 1.f / sqrtf(var + 1e-12f);
    float r0 = d0 * inv * g[c0] + bb[c0];
    float r1 = d1 * inv * g[c1] + bb[c1];
    size_t o = (size_t)row * D_;
    out[o + c0] = r0;
    out[o + c1] = r1;
    __nv_bfloat16 h0, h1, l0, l1;
    split1(r0, h0, l0);
    split1(r1, h1, l1);
    oh[o + c0] = h0; oh[o + c1] = h1;
    ol[o + c0] = l0; ol[o + c1] = l1;
}

// ---------------- mma.sync flash attention (split bf16) ----------------
// Block: 128 threads (4 warps), each warp owns 16 q-rows of a 64-row q tile.
// K/V processed in 64-key tiles; online softmax in registers (FA2 layout).
// QKV input: fused split bf16 [NROWS, 1536] (q|k|v per head-col block).
#define AT_ST 72
#define AT_MATB (64 * AT_ST * 2)     // 9216 bytes per matrix tile
#define ATTN_SMEM (6 * AT_MATB + 256)

__global__ __launch_bounds__(128)
void attn_mma(const __nv_bfloat16* __restrict__ QKVh, const __nv_bfloat16* __restrict__ QKVl,
              const int* __restrict__ mask,
              __nv_bfloat16* __restrict__ Oh, __nv_bfloat16* __restrict__ Ol)
{
    extern __shared__ char sm8[];
    const uint32_t sb = smem_u32(sm8);
    const uint32_t sQH = sb, sQL = sb + AT_MATB;
    const uint32_t sKH = sb + 2 * AT_MATB, sKL = sb + 3 * AT_MATB;
    const uint32_t sVH = sb + 4 * AT_MATB, sVL = sb + 5 * AT_MATB;
    int* maskS = (int*)(sm8 + 6 * AT_MATB);

    const int qt = blockIdx.x, h = blockIdx.y, b = blockIdx.z;
    const int tid = threadIdx.x, lane = tid & 31, wq = tid >> 5;
    const int g = lane >> 2, t4 = lane & 3;

    const int a_r = (lane < 16) ? lane : lane - 16;
    const int a_k = (lane < 16) ? 0 : 8;
    const int b_r = ((lane >> 4) << 3) + (lane & 7);
    const int b_k = ((lane >> 3) & 1) << 3;
    const int v_r = (lane & 7) + (((lane >> 3) & 1) << 3);   // key (k) index
    const int v_n = ((lane >> 4) & 1) << 3;                  // dh (n) offset

    // load Q tile (hi+lo): 64 rows x 64 halves
#pragma unroll
    for (int i = 0; i < 4; i++) {
        int u = tid + i * 128;
        int r = u >> 3, c8 = (u & 7) << 3;
        size_t gofs = (size_t)(b * S_ + qt * 64 + r) * QKVN + h * DH_ + c8;
        uint32_t so = (uint32_t)(r * AT_ST + c8) * 2;
        cp16(sQH + so, QKVh + gofs);
        cp16(sQL + so, QKVl + gofs);
    }
    CP_COMMIT();

    float oacc[8][4];
#pragma unroll
    for (int i = 0; i < 8; i++)
#pragma unroll
        for (int j = 0; j < 4; j++) oacc[i][j] = 0.f;
    float m0 = NEG_INF, m1 = NEG_INF, l0 = 0.f, l1 = 0.f;

    for (int kt = 0; kt < 8; kt++) {
        __syncthreads();
#pragma unroll
        for (int i = 0; i < 4; i++) {
            int u = tid + i * 128;
            int r = u >> 3, c8 = (u & 7) << 3;
            size_t grow = (size_t)(b * S_ + kt * 64 + r) * QKVN + h * DH_;
            uint32_t so = (uint32_t)(r * AT_ST + c8) * 2;
            cp16(sKH + so, QKVh + grow + 512 + c8);
            cp16(sKL + so, QKVl + grow + 512 + c8);
            cp16(sVH + so, QKVh + grow + 1024 + c8);
            cp16(sVL + so, QKVl + grow + 1024 + c8);
        }
        if (tid < 64) maskS[tid] = mask[b * S_ + kt * 64 + tid];
        CP_COMMIT();
        CP_WAIT0();
        __syncthreads();

        // ---- scores: S = Q K^T (split, 3 MMA) ----
        float sacc[8][4];
#pragma unroll
        for (int i = 0; i < 8; i++)
#pragma unroll
            for (int j = 0; j < 4; j++) sacc[i][j] = 0.f;

#pragma unroll
        for (int ks = 0; ks < 4; ks++) {
            uint32_t qh[4], ql[4];
            uint32_t qoff = (uint32_t)((wq * 16 + a_r) * AT_ST + ks * 16 + a_k) * 2;
            LDSM4(qh[0], qh[1], qh[2], qh[3], sQH + qoff);
            LDSM4(ql[0], ql[1], ql[2], ql[3], sQL + qoff);
#pragma unroll
            for (int nb2 = 0; nb2 < 4; nb2++) {
                uint32_t kh[4], kl[4];
                uint32_t koff = (uint32_t)((nb2 * 16 + b_r) * AT_ST + ks * 16 + b_k) * 2;
                LDSM4(kh[0], kh[1], kh[2], kh[3], sKH + koff);
                LDSM4(kl[0], kl[1], kl[2], kl[3], sKL + koff);
                uint32_t f0[2] = {kh[0], kh[1]}, f1[2] = {kh[2], kh[3]};
                uint32_t e0[2] = {kl[0], kl[1]}, e1[2] = {kl[2], kl[3]};
                MMA16816(sacc[nb2 * 2],     qh, f0);
                MMA16816(sacc[nb2 * 2],     qh, e0);
                MMA16816(sacc[nb2 * 2],     ql, f0);
                MMA16816(sacc[nb2 * 2 + 1], qh, f1);
                MMA16816(sacc[nb2 * 2 + 1], qh, e1);
                MMA16816(sacc[nb2 * 2 + 1], ql, f1);
            }
        }

        // ---- scale + mask ----
#pragma unroll
        for (int nb = 0; nb < 8; nb++) {
            int c = (nb << 3) + (t4 << 1);
            bool z0 = (maskS[c] == 0), z1 = (maskS[c + 1] == 0);
            sacc[nb][0] = z0 ? NEG_INF : sacc[nb][0] * 0.125f;
            sacc[nb][1] = z1 ? NEG_INF : sacc[nb][1] * 0.125f;
            sacc[nb][2] = z0 ? NEG_INF : sacc[nb][2] * 0.125f;
            sacc[nb][3] = z1 ? NEG_INF : sacc[nb][3] * 0.125f;
        }

        // ---- online softmax (rows g and g+8) ----
        float t0 = NEG_INF, t1 = NEG_INF;
#pragma unroll
        for (int nb = 0; nb < 8; nb++) {
            t0 = fmaxf(t0, fmaxf(sacc[nb][0], sacc[nb][1]));
            t1 = fmaxf(t1, fmaxf(sacc[nb][2], sacc[nb][3]));
        }
        t0 = fmaxf(t0, __shfl_xor_sync(0xffffffffu, t0, 1));
        t0 = fmaxf(t0, __shfl_xor_sync(0xffffffffu, t0, 2));
        t1 = fmaxf(t1, __shfl_xor_sync(0xffffffffu, t1, 1));
        t1 = fmaxf(t1, __shfl_xor_sync(0xffffffffu, t1, 2));
        float m0n = fmaxf(m0, t0), m1n = fmaxf(m1, t1);
        float me0 = (m0n == NEG_INF) ? 0.f : m0n;
        float me1 = (m1n == NEG_INF) ? 0.f : m1n;
        float alpha0 = __expf(m0 - me0);   // m0=-inf -> 0
        float alpha1 = __expf(m1 - me1);
        m0 = m0n; m1 = m1n;

        float s0 = 0.f, s1 = 0.f;
#pragma unroll
        for (int nb = 0; nb < 8; nb++) {
            float p0 = (sacc[nb][0] == NEG_INF) ? 0.f : __expf(sacc[nb][0] - me0);
            float p1 = (sacc[nb][1] == NEG_INF) ? 0.f : __expf(sacc[nb][1] - me0);
            float p2 = (sacc[nb][2] == NEG_INF) ? 0.f : __expf(sacc[nb][2] - me1);
            float p3 = (sacc[nb][3] == NEG_INF) ? 0.f : __expf(sacc[nb][3] - me1);
            sacc[nb][0] = p0; sacc[nb][1] = p1; sacc[nb][2] = p2; sacc[nb][3] = p3;
            s0 += p0 + p1; s1 += p2 + p3;
        }
        s0 += __shfl_xor_sync(0xffffffffu, s0, 1);
        s0 += __shfl_xor_sync(0xffffffffu, s0, 2);
        s1 += __shfl_xor_sync(0xffffffffu, s1, 1);
        s1 += __shfl_xor_sync(0xffffffffu, s1, 2);
        l0 = l0 * alpha0 + s0;
        l1 = l1 * alpha1 + s1;
#pragma unroll
        for (int nb = 0; nb < 8; nb++) {
            oacc[nb][0] *= alpha0; oacc[nb][1] *= alpha0;
            oacc[nb][2] *= alpha1; oacc[nb][3] *= alpha1;
        }

        // ---- O += P V (split P, split V, 3 MMA) ----
#pragma unroll
        for (int ks = 0; ks < 4; ks++) {
            const float* sa = sacc[2 * ks];
            const float* sc = sacc[2 * ks + 1];
            float ha0, ha1, ha2, ha3, hb0, hb1, hb2, hb3;
            {
                __nv_bfloat16 hh, ll;
                // compute hi parts; lo = p - hi
                ha0 = 0; ha1 = 0; ha2 = 0; ha3 = 0; hb0 = 0; hb1 = 0; hb2 = 0; hb3 = 0;
                (void)hh; (void)ll;
            }
            uint32_t ph[4], pl[4];
            {
                __nv_bfloat16 h0, l0b, h1, l1b;
                split1(sa[0], h0, l0b); split1(sa[1], h1, l1b);
                ph[0] = ((uint32_t)*(uint16_t*)&h1 << 16) | *(uint16_t*)&h0;
                pl[0] = ((uint32_t)*(uint16_t*)&l1b << 16) | *(uint16_t*)&l0b;
                split1(sa[2], h0, l0b); split1(sa[3], h1, l1b);
                ph[1] = ((uint32_t)*(uint16_t*)&h1 << 16) | *(uint16_t*)&h0;
                pl[1] = ((uint32_t)*(uint16_t*)&l1b << 16) | *(uint16_t*)&l0b;
                split1(sc[0], h0, l0b); split1(sc[1], h1, l1b);
                ph[2] = ((uint32_t)*(uint16_t*)&h1 << 16) | *(uint16_t*)&h0;
                pl[2] = ((uint32_t)*(uint16_t*)&l1b << 16) | *(uint16_t*)&l0b;
                split1(sc[2], h0, l0b); split1(sc[3], h1, l1b);
                ph[3] = ((uint32_t)*(uint16_t*)&h1 << 16) | *(uint16_t*)&h0;
                pl[3] = ((uint32_t)*(uint16_t*)&l1b << 16) | *(uint16_t*)&l0b;
            }
#pragma unroll
            for (int nb2 = 0; nb2 < 4; nb2++) {
                uint32_t vh[4], vl[4];
                uint32_t voff = (uint32_t)((ks * 16 + v_r) * AT_ST + nb2 * 16 + v_n) * 2;
                LDSM4T(vh[0], vh[1], vh[2], vh[3], sVH + voff);
                LDSM4T(vl[0], vl[1], vl[2], vl[3], sVL + voff);
                uint32_t f0[2] = {vh[0], vh[1]}, f1[2] = {vh[2], vh[3]};
                uint32_t e0[2] = {vl[0], vl[1]}, e1[2] = {vl[2], vl[3]};
                MMA16816(oacc[nb2 * 2],     ph, f0);
                MMA16816(oacc[nb2 * 2],     ph, e0);
                MMA16816(oacc[nb2 * 2],     pl, f0);
                MMA16816(oacc[nb2 * 2 + 1], ph, f1);
                MMA16816(oacc[nb2 * 2 + 1], ph, e1);
                MMA16816(oacc[nb2 * 2 + 1], pl, f1);
            }
        }
    }

    // ---- epilogue: O/l, split, store ctx ----
    float inv0 = 1.f / l0, inv1 = 1.f / l1;
    int row0 = b * S_ + qt * 64 + wq * 16 + g;
#pragma unroll
    for (int nb = 0; nb < 8; nb++) {
        int col = h * DH_ + nb * 8 + t4 * 2;
        float v0 = oacc[nb][0] * inv0, v1 = oacc[nb][1] * inv0;
        float v2 = oacc[nb][2] * inv1, v3 = oacc[nb][3] * inv1;
        __nv_bfloat16 h0, l0b, h1, l1b;
        split1(v0, h0, l0b); split1(v1, h1, l1b);
        *(__nv_bfloat162*)(Oh + (size_t)row0 * D_ + col) = __nv_bfloat162(h0, h1);
        *(__nv_bfloat162*)(Ol + (size_t)row0 * D_ + col) = __nv_bfloat162(l0b, l1b);
        split1(v2, h0, l0b); split1(v3, h1, l1b);
        *(__nv_bfloat162*)(Oh + (size_t)(row0 + 8) * D_ + col) = __nv_bfloat162(h0, h1);
        *(__nv_bfloat162*)(Ol + (size_t)(row0 + 8) * D_ + col) = __nv_bfloat162(l0b, l1b);
    }
}

// ---------------- orchestration ----------------
extern "C" void kernel_launch(void* const* d_in, const int* in_sizes, int n_in,
                              void* d_out, int out_size)
{
    (void)in_sizes; (void)n_in; (void)out_size;
    const float* video    = (const float*)d_in[0];
    const float* question = (const float*)d_in[1];
    const int*   mask     = (const int*)  d_in[2];
    const float* pos_emb  = (const float*)d_in[3];
    const float* mod_emb  = (const float*)d_in[4];
    const float* Wv   = (const float*)d_in[5];
    const float* bv   = (const float*)d_in[6];
    const float* nv_g = (const float*)d_in[7];
    const float* nv_b = (const float*)d_in[8];
    const float* emb_g= (const float*)d_in[9];
    const float* emb_b= (const float*)d_in[10];
    const float* Wq   = (const float*)d_in[11];
    const float* bq   = (const float*)d_in[12];
    const float* Wk   = (const float*)d_in[13];
    const float* bk   = (const float*)d_in[14];
    const float* Wva  = (const float*)d_in[15];
    const float* bva  = (const float*)d_in[16];
    const float* Wo   = (const float*)d_in[17];
    const float* bo   = (const float*)d_in[18];
    const float* ln1_g= (const float*)d_in[19];
    const float* ln1_b= (const float*)d_in[20];
    const float* W1   = (const float*)d_in[21];
    const float* b1   = (const float*)d_in[22];
    const float* W2   = (const float*)d_in[23];
    const float* b2   = (const float*)d_in[24];
    const float* ln2_g= (const float*)d_in[25];
    const float* ln2_b= (const float*)d_in[26];

    float *x, *t, *bqkv;
    cudaGetSymbolAddress((void**)&x, g_x);
    cudaGetSymbolAddress((void**)&t, g_t);
    cudaGetSymbolAddress((void**)&bqkv, g_bqkv);

    __nv_bfloat16 *ah, *al, *bh, *bl, *qkvh, *qkvl, *wvh, *wvl, *wqkvh, *wqkvl,
                  *woh, *wol, *w1h, *w1l, *w2h, *w2l;
    cudaGetSymbolAddress((void**)&ah,    g_ah);
    cudaGetSymbolAddress((void**)&al,    g_al);
    cudaGetSymbolAddress((void**)&bh,    g_bh);
    cudaGetSymbolAddress((void**)&bl,    g_bl);
    cudaGetSymbolAddress((void**)&qkvh,  g_qkvh);
    cudaGetSymbolAddress((void**)&qkvl,  g_qkvl);
    cudaGetSymbolAddress((void**)&wvh,   g_wvh);
    cudaGetSymbolAddress((void**)&wvl,   g_wvl);
    cudaGetSymbolAddress((void**)&wqkvh, g_wqkvh);
    cudaGetSymbolAddress((void**)&wqkvl, g_wqkvl);
    cudaGetSymbolAddress((void**)&woh,   g_woh);
    cudaGetSymbolAddress((void**)&wol,   g_wol);
    cudaGetSymbolAddress((void**)&w1h,   g_w1h);
    cudaGetSymbolAddress((void**)&w1l,   g_w1l);
    cudaGetSymbolAddress((void**)&w2h,   g_w2h);
    cudaGetSymbolAddress((void**)&w2l,   g_w2l);

    cudaFuncSetAttribute(attn_mma, cudaFuncAttributeMaxDynamicSharedMemorySize, ATTN_SMEM);
    cudaFuncSetAttribute(mgemm<false, false, false>, cudaFuncAttributeMaxDynamicSharedMemorySize, MG_SMEM);
    cudaFuncSetAttribute(mgemm<false, true,  false>, cudaFuncAttributeMaxDynamicSharedMemorySize, MG_SMEM);
    cudaFuncSetAttribute(mgemm<true,  false, true >, cudaFuncAttributeMaxDynamicSharedMemorySize, MG_SMEM);
    cudaFuncSetAttribute(mgemm<false, false, true >, cudaFuncAttributeMaxDynamicSharedMemorySize, MG_SMEM);

    // ---- weight conversion (transpose + split), once per launch ----
    tsplit_k<<<dim3(512 / 32, 1024 / 32), 256>>>(Wv, wvh, wvl, 1024, 512);
    for (int i = 0; i < 2; i++) {
        size_t od = (size_t)i * 512 * 512;
        size_t oq = (size_t)i * QKVN * 512;
        tsplit_k<<<dim3(16, 16), 256>>>(Wq  + od, wqkvh + oq,              wqkvl + oq,              512, 512);
        tsplit_k<<<dim3(16, 16), 256>>>(Wk  + od, wqkvh + oq + 512 * 512,  wqkvl + oq + 512 * 512,  512, 512);
        tsplit_k<<<dim3(16, 16), 256>>>(Wva + od, wqkvh + oq + 1024 * 512, wqkvl + oq + 1024 * 512, 512, 512);
        tsplit_k<<<dim3(16, 16), 256>>>(Wo  + od, woh + od, wol + od, 512, 512);
        size_t of = (size_t)i * 512 * 2048;
        tsplit_k<<<dim3(2048 / 32, 512 / 32), 256>>>(W1 + of, w1h + of, w1l + of, 512, 2048);
        tsplit_k<<<dim3(512 / 32, 2048 / 32), 256>>>(W2 + of, w2h + of, w2l + of, 2048, 512);
        pack_bias3<<<2, 256>>>(bq + i * D_, bk + i * D_, bva + i * D_, bqkv + i * QKVN);
    }

    // ---- video projection + LN(nv) ----
    split_k<<<2048, 256>>>((const float4*)video, (__nv_bfloat162*)ah,
                           (__nv_bfloat162*)al, (int)((size_t)VROWS * FD_ / 4));
    mgemm<false, false, false><<<dim3(D_ / 128, VROWS / 128), 256, MG_SMEM>>>(
        ah, al, wvh, wvl, bv, nullptr, t, nullptr, nullptr, VROWS, D_, FD_);
    ln512<false><<<VROWS, 256>>>(t, nv_g, nv_b, t, nullptr, nullptr);

    // ---- assemble x = LN(concat + pos + mod); writes x fp32 + ah/al split ----
    assemble_ln<<<NROWS, 256>>>(question, t, pos_emb, mod_emb, emb_g, emb_b, x, ah, al);

    for (int i = 0; i < 2; i++) {
        size_t od = (size_t)i * 512 * 512;
        size_t oq = (size_t)i * QKVN * 512;
        size_t of = (size_t)i * 512 * 2048;
        const float* boi = bo + i * D_;
        const float* b1i = b1 + i * FF_;
        const float* b2i = b2 + i * D_;

        // fused QKV projection (split output)
        mgemm<false, false, true><<<dim3(QKVN / 128, NROWS / 128), 256, MG_SMEM>>>(
            ah, al, wqkvh + oq, wqkvl + oq, bqkv + i * QKVN, nullptr,
            nullptr, qkvh, qkvl, NROWS, QKVN, D_);

        // attention -> ctx split (bh/bl viewed [NROWS, D])
        attn_mma<<<dim3(S_ / 64, H_, B_), 128, ATTN_SMEM>>>(qkvh, qkvl, mask, bh, bl);

        // output projection + residual, LN1 (-> x fp32 + ah/al split)
        mgemm<false, true, false><<<dim3(4, NROWS / 128), 256, MG_SMEM>>>(
            bh, bl, woh + od, wol + od, boi, x, t, nullptr, nullptr, NROWS, D_, D_);
        ln512<true><<<NROWS, 256>>>(t, ln1_g + i * D_, ln1_b + i * D_, x, ah, al);

        // FFN
        mgemm<true, false, true><<<dim3(FF_ / 128, NROWS / 128), 256, MG_SMEM>>>(
            ah, al, w1h + of, w1l + of, b1i, nullptr, nullptr, bh, bl, NROWS, FF_, D_);
        mgemm<false, true, false><<<dim3(4, NROWS / 128), 256, MG_SMEM>>>(
            bh, bl, w2h + of, w2l + of, b2i, x, t, nullptr, nullptr, NROWS, D_, FF_);

        float* out = (i == 1) ? (float*)d_out : x;
        ln512<true><<<NROWS, 256>>>(t, ln2_g + i * D_, ln2_b + i * D_, out, ah, al);
    }
}